// round 1
// baseline (speedup 1.0000x reference)
#include <cuda_runtime.h>
#include <cuda_bf16.h>

#define NB   8
#define CC   256
#define CQK  32
#define LL   4096

// ---------------- scratch (device globals; no allocation allowed) ----------
__device__ float g_Wt[CC * 320];                 // fused weights, channel-major: Wt[c][o], o: 0-31 q, 32-63 k, 64-319 v
__device__ float g_q [NB * CQK * LL];            // (N, 32, L)
__device__ float g_k [NB * CQK * LL];            // (N, 32, L)
__device__ float g_vT[NB * LL * CC];             // (N, L, 256)  -- transposed V

// ---------------- packed f32x2 helpers -------------------------------------
__device__ __forceinline__ unsigned long long pack2(float a, float b) {
    unsigned long long r;
    asm("mov.b64 %0, {%1, %2};" : "=l"(r) : "f"(a), "f"(b));
    return r;
}
__device__ __forceinline__ void unpack2(unsigned long long v, float& lo, float& hi) {
    asm("mov.b64 {%0, %1}, %2;" : "=f"(lo), "=f"(hi) : "l"(v));
}
__device__ __forceinline__ void ffma2(unsigned long long& d, unsigned long long a, unsigned long long b) {
    asm("fma.rn.f32x2 %0, %1, %2, %0;" : "+l"(d) : "l"(a), "l"(b));
}
__device__ __forceinline__ void fmul2(unsigned long long& d, unsigned long long a) {
    asm("mul.rn.f32x2 %0, %1, %0;" : "+l"(d) : "l"(a));
}

// ---------------- kernel 1: weight transpose --------------------------------
__global__ void wtrans_kernel(const float* __restrict__ Wq,
                              const float* __restrict__ Wk,
                              const float* __restrict__ Wv) {
    int idx = blockIdx.x * 256 + threadIdx.x;   // 320*256 total
    if (idx >= 320 * 256) return;
    int o = idx >> 8;          // 0..319
    int c = idx & 255;
    float v;
    if (o < 32)       v = Wq[o * 256 + c];
    else if (o < 64)  v = Wk[(o - 32) * 256 + c];
    else              v = Wv[(o - 64) * 256 + c];
    g_Wt[c * 320 + o] = v;
}

// ---------------- kernel 2: fused QKV projection -----------------------------
// grid (L/128, N), 256 threads, 128KB dyn smem
__global__ __launch_bounds__(256, 1)
void proj_kernel(const float* __restrict__ x,
                 const float* __restrict__ bq,
                 const float* __restrict__ bk,
                 const float* __restrict__ bv) {
    extern __shared__ float xs[];   // [256][128]
    const int n  = blockIdx.y;
    const int l0 = blockIdx.x * 128;
    const int tid = threadIdx.x;

    // load x tile, coalesced
    const float* xb = x + ((size_t)n << 20) + l0;   // n*256*4096
    #pragma unroll 4
    for (int idx = tid; idx < 256 * 128; idx += 256) {
        int c = idx >> 7, l = idx & 127;
        xs[idx] = xb[(c << 12) + l];
    }
    __syncthreads();

    const int warp = tid >> 5, lane = tid & 31;
    const int lb = lane * 4;

    for (int og = 0; og < 10; og++) {
        const int obase = og * 32 + warp * 4;
        float bias[4];
        #pragma unroll
        for (int r = 0; r < 4; r++) {
            int o = obase + r;
            bias[r] = (o < 32) ? bq[o] : (o < 64) ? bk[o - 32] : bv[o - 64];
        }
        float4 acc0 = make_float4(bias[0], bias[0], bias[0], bias[0]);
        float4 acc1 = make_float4(bias[1], bias[1], bias[1], bias[1]);
        float4 acc2 = make_float4(bias[2], bias[2], bias[2], bias[2]);
        float4 acc3 = make_float4(bias[3], bias[3], bias[3], bias[3]);

        #pragma unroll 4
        for (int c = 0; c < 256; c++) {
            float4 w  = __ldg((const float4*)&g_Wt[c * 320 + obase]);
            float4 xv = *(const float4*)&xs[c * 128 + lb];
            acc0.x += w.x * xv.x; acc0.y += w.x * xv.y; acc0.z += w.x * xv.z; acc0.w += w.x * xv.w;
            acc1.x += w.y * xv.x; acc1.y += w.y * xv.y; acc1.z += w.y * xv.z; acc1.w += w.y * xv.w;
            acc2.x += w.z * xv.x; acc2.y += w.z * xv.y; acc2.z += w.z * xv.z; acc2.w += w.z * xv.w;
            acc3.x += w.w * xv.x; acc3.y += w.w * xv.y; acc3.z += w.w * xv.z; acc3.w += w.w * xv.w;
        }

        float4 acc[4] = {acc0, acc1, acc2, acc3};
        if (obase < 64) {
            float* dst = (obase < 32) ? g_q : g_k;
            int ob = (obase < 32) ? obase : obase - 32;
            #pragma unroll
            for (int r = 0; r < 4; r++) {
                *(float4*)&dst[(((size_t)n * CQK + ob + r) << 12) + l0 + lb] = acc[r];
            }
        } else {
            int vo = obase - 64;
            #pragma unroll
            for (int s = 0; s < 4; s++) {
                float4 vv;
                vv.x = (&acc[0].x)[s]; vv.y = (&acc[1].x)[s];
                vv.z = (&acc[2].x)[s]; vv.w = (&acc[3].x)[s];
                *(float4*)&g_vT[(((size_t)n << 12) + l0 + lb + s) * CC + vo] = vv;
            }
        }
    }
}

// ---------------- kernel 3: fused flash attention ----------------------------
// grid (L/64, N), 256 threads, smem = 25216 floats = 100864 B, 2 CTA/SM
#define SM_Q   0
#define SM_K   2048
#define SM_P   4096          // stride 68
#define SM_V   8448          // stride 260
#define SM_AUX 25088         // [0..63] alpha, [64..127] l

__global__ __launch_bounds__(256, 2)
void attn_kernel(const float* __restrict__ x,
                 const float* __restrict__ gamma,
                 float* __restrict__ out) {
    extern __shared__ float sm[];
    float* q_s = sm + SM_Q;
    float* k_s = sm + SM_K;
    float* p_s = sm + SM_P;
    float* v_s = sm + SM_V;
    float* aux = sm + SM_AUX;

    const int n  = blockIdx.y;
    const int i0 = blockIdx.x * 64;
    const int tid = threadIdx.x;

    // S-phase ids: thread owns i = ti*4+r (r<4), j = tj*4+t (t<4)
    const int ti = tid >> 4, tj = tid & 15;
    // PV-phase ids: warp covers c = w*32..w*32+31; lane: i = ig*8+r (r<8), c = cbase+ 0..7
    const int w = tid >> 5, lane = tid & 31;
    const int ig = lane >> 2, cg = lane & 3;
    const int cbase = w * 32 + cg * 8;

    // load Q tile
    {
        const float* qb = g_q + ((size_t)n * CQK << 12) + i0;
        #pragma unroll
        for (int idx = tid; idx < 2048; idx += 256) {
            int d = idx >> 6, i = idx & 63;
            q_s[idx] = qb[(d << 12) + i];
        }
    }

    float mrun[4], lrun[4];
    #pragma unroll
    for (int r = 0; r < 4; r++) { mrun[r] = -1e30f; lrun[r] = 0.f; }
    unsigned long long O[8][4];
    #pragma unroll
    for (int r = 0; r < 8; r++)
        #pragma unroll
        for (int t = 0; t < 4; t++) O[r][t] = 0ull;

    const float4* q4 = (const float4*)q_s;
    const float4* k4 = (const float4*)k_s;
    const float4* p4 = (const float4*)p_s;
    const unsigned long long* v2 = (const unsigned long long*)v_s;

    for (int jt = 0; jt < 64; jt++) {
        const int j0 = jt * 64;
        __syncthreads();
        // load K tile (32 x 64)
        {
            const float* kb = g_k + ((size_t)n * CQK << 12) + j0;
            #pragma unroll
            for (int idx = tid; idx < 2048; idx += 256) {
                int d = idx >> 6, j = idx & 63;
                k_s[idx] = kb[(d << 12) + j];
            }
        }
        // load V tile (64 x 256), stride 260
        {
            const float4* vb = (const float4*)(g_vT + (((size_t)n << 12) + j0) * CC);
            #pragma unroll
            for (int idx = tid; idx < 4096; idx += 256) {
                int j = idx >> 6, c4 = idx & 63;
                float4 vv = __ldg(&vb[j * 64 + c4]);
                *(float4*)&v_s[j * 260 + c4 * 4] = vv;
            }
        }
        __syncthreads();

        // ---- S = Q^T K (4i x 4j per thread) ----
        float s[4][4];
        #pragma unroll
        for (int r = 0; r < 4; r++)
            #pragma unroll
            for (int t = 0; t < 4; t++) s[r][t] = 0.f;

        #pragma unroll
        for (int d = 0; d < 32; d++) {
            float4 qv = q4[d * 16 + ti];
            float4 kv = k4[d * 16 + tj];
            const float* qp = &qv.x;
            const float* kp = &kv.x;
            #pragma unroll
            for (int r = 0; r < 4; r++)
                #pragma unroll
                for (int t = 0; t < 4; t++) s[r][t] += qp[r] * kp[t];
        }

        // ---- online softmax ----
        #pragma unroll
        for (int r = 0; r < 4; r++) {
            float mx = fmaxf(fmaxf(s[r][0], s[r][1]), fmaxf(s[r][2], s[r][3]));
            #pragma unroll
            for (int off = 8; off >= 1; off >>= 1)
                mx = fmaxf(mx, __shfl_xor_sync(0xffffffffu, mx, off));
            float mn = fmaxf(mrun[r], mx);
            float al = __expf(mrun[r] - mn);
            mrun[r] = mn;
            float rs = 0.f;
            #pragma unroll
            for (int t = 0; t < 4; t++) {
                float p = __expf(s[r][t] - mn);
                s[r][t] = p;
                rs += p;
            }
            #pragma unroll
            for (int off = 8; off >= 1; off >>= 1)
                rs += __shfl_xor_sync(0xffffffffu, rs, off);
            lrun[r] = al * lrun[r] + rs;
            #pragma unroll
            for (int t = 0; t < 4; t++)
                p_s[(tj * 4 + t) * 68 + ti * 4 + r] = s[r][t];
            if (tj == 0) aux[ti * 4 + r] = al;
        }
        __syncthreads();

        // rescale O by alpha (PV i-ownership)
        #pragma unroll
        for (int r = 0; r < 8; r++) {
            float a = aux[ig * 8 + r];
            unsigned long long ap = pack2(a, a);
            #pragma unroll
            for (int t = 0; t < 4; t++) fmul2(O[r][t], ap);
        }

        // ---- O += P V  (packed f32x2) ----
        #pragma unroll 2
        for (int j = 0; j < 64; j++) {
            float4 pA = p4[j * 17 + ig * 2];
            float4 pB = p4[j * 17 + ig * 2 + 1];
            unsigned long long va = v2[j * 130 + (cbase >> 1) + 0];
            unsigned long long vb = v2[j * 130 + (cbase >> 1) + 1];
            unsigned long long vc = v2[j * 130 + (cbase >> 1) + 2];
            unsigned long long vd = v2[j * 130 + (cbase >> 1) + 3];
            float pr[8] = {pA.x, pA.y, pA.z, pA.w, pB.x, pB.y, pB.z, pB.w};
            #pragma unroll
            for (int r = 0; r < 8; r++) {
                unsigned long long pp = pack2(pr[r], pr[r]);
                ffma2(O[r][0], pp, va);
                ffma2(O[r][1], pp, vb);
                ffma2(O[r][2], pp, vc);
                ffma2(O[r][3], pp, vd);
            }
        }
    }

    // publish l, then finalize
    __syncthreads();
    if (tj == 0) {
        #pragma unroll
        for (int r = 0; r < 4; r++) aux[64 + ti * 4 + r] = lrun[r];
    }
    __syncthreads();

    const float g = __ldg(gamma);
    #pragma unroll
    for (int r = 0; r < 8; r++) {
        const int il = ig * 8 + r;
        const float linv = 1.0f / aux[64 + il];
        const int i = i0 + il;
        #pragma unroll
        for (int t = 0; t < 4; t++) {
            float lo, hi;
            unpack2(O[r][t], lo, hi);
            int c0 = cbase + 2 * t;
            size_t idx0 = (((size_t)n * CC + c0) << 12) + i;
            size_t idx1 = idx0 + ((size_t)1 << 12);
            out[idx0] = g * (lo * linv) + x[idx0];
            out[idx1] = g * (hi * linv) + x[idx1];
        }
    }
}

// ---------------- launch ----------------------------------------------------
extern "C" void kernel_launch(void* const* d_in, const int* in_sizes, int n_in,
                              void* d_out, int out_size) {
    const float* x     = (const float*)d_in[0];
    const float* Wq    = (const float*)d_in[1];
    const float* bq    = (const float*)d_in[2];
    const float* Wk    = (const float*)d_in[3];
    const float* bk    = (const float*)d_in[4];
    const float* Wv    = (const float*)d_in[5];
    const float* bv    = (const float*)d_in[6];
    const float* gamma = (const float*)d_in[7];
    float* out = (float*)d_out;

    cudaFuncSetAttribute(proj_kernel, cudaFuncAttributeMaxDynamicSharedMemorySize, 131072);
    cudaFuncSetAttribute(attn_kernel, cudaFuncAttributeMaxDynamicSharedMemorySize, 100864);

    wtrans_kernel<<<(320 * 256 + 255) / 256, 256>>>(Wq, Wk, Wv);
    proj_kernel<<<dim3(LL / 128, NB), 256, 131072>>>(x, bq, bk, bv);
    attn_kernel<<<dim3(LL / 64, NB), 256, 100864>>>(x, gamma, out);
}